// round 1
// baseline (speedup 1.0000x reference)
#include <cuda_runtime.h>
#include <cstdint>

#define N_NODES  100000
#define N_HEDGES 25000
#define NNZ      1600000
#define CH       128   // IN_CH == HEADS_OUT == 128

// Scratch: device globals (no allocation allowed anywhere).
__device__ float g_Xp[(size_t)N_NODES * CH];   // projected node features (51.2 MB)
__device__ float g_Xe[(size_t)N_HEDGES * CH];  // hyperedge accumulator  (12.8 MB)

// ---------------------------------------------------------------------------
// Zero Xe and d_out (harness poisons d_out with 0xAA before timing).
// ---------------------------------------------------------------------------
__global__ void zero_kernel(float4* __restrict__ out4) {
    size_t i = (size_t)blockIdx.x * blockDim.x + threadIdx.x;
    const size_t n_out4 = (size_t)N_NODES * CH / 4;   // 3.2M
    const size_t n_xe4  = (size_t)N_HEDGES * CH / 4;  // 0.8M
    float4 z = make_float4(0.f, 0.f, 0.f, 0.f);
    if (i < n_out4) out4[i] = z;
    if (i < n_xe4)  reinterpret_cast<float4*>(g_Xe)[i] = z;
}

// ---------------------------------------------------------------------------
// GEMM: g_Xp = X[100000,128] @ Wlin[128,128]   (fp32, SMEM-tiled)
// Block: 64 rows x 128 cols, 256 threads, 4x8 register tile, BK=16.
// ---------------------------------------------------------------------------
__global__ __launch_bounds__(256) void gemm_kernel(const float* __restrict__ X,
                                                   const float* __restrict__ W) {
    __shared__ float Xs[64][17];   // +1 pad: column reads conflict-free
    __shared__ float Ws[16][128];

    const int tx   = threadIdx.x & 15;   // 0..15 -> 8 output cols each
    const int ty   = threadIdx.x >> 4;   // 0..15 -> 4 output rows each
    const int row0 = blockIdx.x * 64;

    float acc[4][8];
#pragma unroll
    for (int i = 0; i < 4; i++)
#pragma unroll
        for (int j = 0; j < 8; j++) acc[i][j] = 0.f;

    for (int kk = 0; kk < CH; kk += 16) {
        // Load X tile: 64 rows x 16 cols = 256 float4 (one per thread)
        {
            int r  = threadIdx.x >> 2;        // 0..63
            int c4 = (threadIdx.x & 3) * 4;   // 0,4,8,12
            float4 xv = make_float4(0.f, 0.f, 0.f, 0.f);
            if (row0 + r < N_NODES)
                xv = *reinterpret_cast<const float4*>(X + (size_t)(row0 + r) * CH + kk + c4);
            Xs[r][c4 + 0] = xv.x; Xs[r][c4 + 1] = xv.y;
            Xs[r][c4 + 2] = xv.z; Xs[r][c4 + 3] = xv.w;
        }
        // Load W tile: 16 rows x 128 cols = 512 float4 (two per thread)
#pragma unroll
        for (int i = 0; i < 2; i++) {
            int t  = threadIdx.x + i * 256;
            int wr = t >> 5;            // 0..15
            int wc = (t & 31) * 4;      // 0..124
            *reinterpret_cast<float4*>(&Ws[wr][wc]) =
                *reinterpret_cast<const float4*>(W + (size_t)(kk + wr) * CH + wc);
        }
        __syncthreads();

#pragma unroll
        for (int k = 0; k < 16; k++) {
            float a[4];
#pragma unroll
            for (int i = 0; i < 4; i++) a[i] = Xs[ty * 4 + i][k];
            float b[8];
            *reinterpret_cast<float4*>(&b[0]) = *reinterpret_cast<float4*>(&Ws[k][tx * 8]);
            *reinterpret_cast<float4*>(&b[4]) = *reinterpret_cast<float4*>(&Ws[k][tx * 8 + 4]);
#pragma unroll
            for (int i = 0; i < 4; i++)
#pragma unroll
                for (int j = 0; j < 8; j++) acc[i][j] += a[i] * b[j];
        }
        __syncthreads();
    }

#pragma unroll
    for (int i = 0; i < 4; i++) {
        int row = row0 + ty * 4 + i;
        if (row < N_NODES) {
            float* o = g_Xp + (size_t)row * CH + tx * 8;
            *reinterpret_cast<float4*>(o)     = make_float4(acc[i][0], acc[i][1], acc[i][2], acc[i][3]);
            *reinterpret_cast<float4*>(o + 4) = make_float4(acc[i][4], acc[i][5], acc[i][6], acc[i][7]);
        }
    }
}

// ---------------------------------------------------------------------------
// Vector reduction helper: 16B global float add, no return (REDG).
// ---------------------------------------------------------------------------
__device__ __forceinline__ void red_add_v4(float* addr, float4 v) {
    asm volatile("red.global.add.v4.f32 [%0], {%1, %2, %3, %4};"
                 :: "l"(addr), "f"(v.x), "f"(v.y), "f"(v.z), "f"(v.w)
                 : "memory");
}

// ---------------------------------------------------------------------------
// Stage 1: Xe[dst] += Xp[src]   (one warp per edge, 4 floats per lane)
// ---------------------------------------------------------------------------
__global__ __launch_bounds__(256) void scatter1_kernel(const int* __restrict__ src,
                                                       const int* __restrict__ dst) {
    int gid  = blockIdx.x * blockDim.x + threadIdx.x;
    int e    = gid >> 5;
    int lane = gid & 31;
    if (e >= NNZ) return;
    int s = src[e];
    int d = dst[e];
    float4 v = *(reinterpret_cast<const float4*>(g_Xp + (size_t)s * CH) + lane);
    red_add_v4(g_Xe + (size_t)d * CH + lane * 4, v);
}

// ---------------------------------------------------------------------------
// Stage 2: out[src] += Xe[dst] * degE[dst] * W[dst] * degV[src]
// (degE/W fused at gather; degV distributes over the sum, fused at scatter)
// ---------------------------------------------------------------------------
__global__ __launch_bounds__(256) void scatter2_kernel(const int* __restrict__ src,
                                                       const int* __restrict__ dst,
                                                       const float* __restrict__ degE,
                                                       const float* __restrict__ degV,
                                                       const float* __restrict__ Wbuf,
                                                       float* __restrict__ out) {
    int gid  = blockIdx.x * blockDim.x + threadIdx.x;
    int e    = gid >> 5;
    int lane = gid & 31;
    if (e >= NNZ) return;
    int s = src[e];
    int d = dst[e];
    float scale = degE[d] * Wbuf[d] * degV[s];
    float4 v = *(reinterpret_cast<const float4*>(g_Xe + (size_t)d * CH) + lane);
    v.x *= scale; v.y *= scale; v.z *= scale; v.w *= scale;
    red_add_v4(out + (size_t)s * CH + lane * 4, v);
}

// ---------------------------------------------------------------------------
// Launch
// ---------------------------------------------------------------------------
extern "C" void kernel_launch(void* const* d_in, const int* in_sizes, int n_in,
                              void* d_out, int out_size) {
    const float* X    = (const float*)d_in[0];  // [100000,128]
    const float* Wlin = (const float*)d_in[1];  // [128,128]
    const float* degE = (const float*)d_in[2];  // [25000,1]
    const float* degV = (const float*)d_in[3];  // [100000,1]
    const float* Wbuf = (const float*)d_in[4];  // [25000,1]
    const int*   src  = (const int*)d_in[5];    // [1600000]
    const int*   dst  = (const int*)d_in[6];    // [1600000]
    float*       out  = (float*)d_out;          // [100000,128]

    // Zero Xe and out
    {
        const size_t n4 = (size_t)N_NODES * CH / 4;  // 3.2M (covers Xe's 0.8M too)
        int blocks = (int)((n4 + 255) / 256);
        zero_kernel<<<blocks, 256>>>(reinterpret_cast<float4*>(out));
    }

    // GEMM: Xp = X @ Wlin
    {
        int blocks = (N_NODES + 63) / 64;  // 1563
        gemm_kernel<<<blocks, 256>>>(X, Wlin);
    }

    // Stage 1 scatter: node -> hyperedge
    {
        long long total = (long long)NNZ * 32;
        int blocks = (int)((total + 255) / 256);  // 200000
        scatter1_kernel<<<blocks, 256>>>(src, dst);
    }

    // Stage 2 scatter: hyperedge -> node (with fused scalings)
    {
        long long total = (long long)NNZ * 32;
        int blocks = (int)((total + 255) / 256);
        scatter2_kernel<<<blocks, 256>>>(src, dst, degE, degV, Wbuf, out);
    }
}

// round 2
// speedup vs baseline: 1.8005x; 1.8005x over previous
#include <cuda_runtime.h>
#include <cstdint>

#define N_NODES  100000
#define N_HEDGES 25000
#define NNZ      1600000
#define CH       128

// ---------------------------------------------------------------------------
// Device-global scratch (no allocation allowed anywhere)
// ---------------------------------------------------------------------------
__device__ float g_Xp[(size_t)N_NODES * CH];    // projected features (51.2 MB)
__device__ float g_Xe[(size_t)N_HEDGES * CH];   // hyperedge features (12.8 MB)

__device__ int g_cnt_e[N_HEDGES];
__device__ int g_cnt_v[N_NODES];
__device__ int g_rowptr_e[N_HEDGES + 1];
__device__ int g_rowptr_v[N_NODES + 1];
__device__ int g_cur_e[N_HEDGES];
__device__ int g_cur_v[N_NODES];
__device__ int g_src_by_e[NNZ];   // src node per CSR(dst) slot
__device__ int g_dst_by_v[NNZ];   // dst hedge per CSR(src) slot
__device__ int g_bsum_e[128];
__device__ int g_bsum_v[128];

// ---------------------------------------------------------------------------
// CSR build: histogram
// ---------------------------------------------------------------------------
__global__ void hist_kernel(const int* __restrict__ src, const int* __restrict__ dst) {
    int i = blockIdx.x * blockDim.x + threadIdx.x;
    if (i >= NNZ) return;
    atomicAdd(&g_cnt_e[dst[i]], 1);
    atomicAdd(&g_cnt_v[src[i]], 1);
}

// Per-block reduction of counts -> block sums
__global__ void reduce_kernel(const int* __restrict__ cnt, int n, int* __restrict__ bsum) {
    __shared__ int s[1024];
    int tid = threadIdx.x;
    int i = blockIdx.x * 1024 + tid;
    s[tid] = (i < n) ? cnt[i] : 0;
    __syncthreads();
#pragma unroll
    for (int o = 512; o > 0; o >>= 1) {
        if (tid < o) s[tid] += s[tid + o];
        __syncthreads();
    }
    if (tid == 0) bsum[blockIdx.x] = s[0];
}

// Single-block exclusive scan of block sums (nb <= 1024); writes total to *total
__global__ void scan_bsum_kernel(int* __restrict__ bsum, int nb, int* __restrict__ total) {
    __shared__ int s[1024];
    int tid = threadIdx.x;
    int v0 = (tid < nb) ? bsum[tid] : 0;
    s[tid] = v0;
    __syncthreads();
#pragma unroll
    for (int o = 1; o < 1024; o <<= 1) {
        int v = (tid >= o) ? s[tid - o] : 0;
        __syncthreads();
        s[tid] += v;
        __syncthreads();
    }
    if (tid < nb) bsum[tid] = s[tid] - v0;             // exclusive
    if (tid == nb - 1) *total = s[tid];                // grand total -> rowptr[n]
}

// Final pass: per-block exclusive scan + block offset -> rowptr & cursor
__global__ void scan_final_kernel(const int* __restrict__ cnt, int n,
                                  const int* __restrict__ boff,
                                  int* __restrict__ rowptr, int* __restrict__ cur) {
    __shared__ int s[1024];
    int tid = threadIdx.x;
    int i = blockIdx.x * 1024 + tid;
    int v0 = (i < n) ? cnt[i] : 0;
    s[tid] = v0;
    __syncthreads();
#pragma unroll
    for (int o = 1; o < 1024; o <<= 1) {
        int v = (tid >= o) ? s[tid - o] : 0;
        __syncthreads();
        s[tid] += v;
        __syncthreads();
    }
    if (i < n) {
        int val = s[tid] - v0 + boff[blockIdx.x];      // exclusive prefix
        rowptr[i] = val;
        cur[i]    = val;
    }
}

// Place edges into both CSRs
__global__ void place_kernel(const int* __restrict__ src, const int* __restrict__ dst) {
    int i = blockIdx.x * blockDim.x + threadIdx.x;
    if (i >= NNZ) return;
    int s = src[i];
    int d = dst[i];
    int p = atomicAdd(&g_cur_e[d], 1);
    g_src_by_e[p] = s;
    int q = atomicAdd(&g_cur_v[s], 1);
    g_dst_by_v[q] = d;
}

// ---------------------------------------------------------------------------
// GEMM: g_Xp = X[100000,128] @ Wlin[128,128]
// 128x128 block tile, 256 threads, 8x8 register tile, BK=16
// ---------------------------------------------------------------------------
__global__ __launch_bounds__(256) void gemm_kernel(const float* __restrict__ X,
                                                   const float* __restrict__ W) {
    __shared__ float Xs[128][17];
    __shared__ float Ws[16][128];

    const int tid  = threadIdx.x;
    const int tx   = tid & 15;    // 16 col-groups of 8
    const int ty   = tid >> 4;    // 16 row-groups of 8
    const int row0 = blockIdx.x * 128;

    float acc[8][8];
#pragma unroll
    for (int i = 0; i < 8; i++)
#pragma unroll
        for (int j = 0; j < 8; j++) acc[i][j] = 0.f;

    for (int kk = 0; kk < CH; kk += 16) {
        // Load X tile: 128 rows x 16 cols = 512 float4 -> 2 per thread
#pragma unroll
        for (int i = 0; i < 2; i++) {
            int t  = tid + i * 256;
            int r  = t >> 2;             // 0..127
            int c4 = (t & 3) * 4;        // 0,4,8,12
            float4 xv = make_float4(0.f, 0.f, 0.f, 0.f);
            if (row0 + r < N_NODES)
                xv = *reinterpret_cast<const float4*>(X + (size_t)(row0 + r) * CH + kk + c4);
            Xs[r][c4 + 0] = xv.x; Xs[r][c4 + 1] = xv.y;
            Xs[r][c4 + 2] = xv.z; Xs[r][c4 + 3] = xv.w;
        }
        // Load W tile: 16 rows x 128 cols = 512 float4 -> 2 per thread
#pragma unroll
        for (int i = 0; i < 2; i++) {
            int t  = tid + i * 256;
            int wr = t >> 5;             // 0..15
            int wc = (t & 31) * 4;       // 0..124
            *reinterpret_cast<float4*>(&Ws[wr][wc]) =
                *reinterpret_cast<const float4*>(W + (size_t)(kk + wr) * CH + wc);
        }
        __syncthreads();

#pragma unroll
        for (int k = 0; k < 16; k++) {
            float a[8];
#pragma unroll
            for (int i = 0; i < 8; i++) a[i] = Xs[ty * 8 + i][k];
            float b[8];
            *reinterpret_cast<float4*>(&b[0]) = *reinterpret_cast<float4*>(&Ws[k][tx * 8]);
            *reinterpret_cast<float4*>(&b[4]) = *reinterpret_cast<float4*>(&Ws[k][tx * 8 + 4]);
#pragma unroll
            for (int i = 0; i < 8; i++)
#pragma unroll
                for (int j = 0; j < 8; j++) acc[i][j] += a[i] * b[j];
        }
        __syncthreads();
    }

#pragma unroll
    for (int i = 0; i < 8; i++) {
        int row = row0 + ty * 8 + i;
        if (row < N_NODES) {
            float* o = g_Xp + (size_t)row * CH + tx * 8;
            *reinterpret_cast<float4*>(o)     = make_float4(acc[i][0], acc[i][1], acc[i][2], acc[i][3]);
            *reinterpret_cast<float4*>(o + 4) = make_float4(acc[i][4], acc[i][5], acc[i][6], acc[i][7]);
        }
    }
}

// ---------------------------------------------------------------------------
// Stage 1 (atomic-free): warp per hyperedge.
// Xe[e] = (sum_{v in e} Xp[v]) * degE[e] * W[e]
// ---------------------------------------------------------------------------
__global__ __launch_bounds__(256) void seg1_kernel(const float* __restrict__ degE,
                                                   const float* __restrict__ Wbuf) {
    int gid  = blockIdx.x * blockDim.x + threadIdx.x;
    int e    = gid >> 5;
    int lane = gid & 31;
    if (e >= N_HEDGES) return;

    int beg = g_rowptr_e[e];
    int end = g_rowptr_e[e + 1];
    const float4* Xp4 = reinterpret_cast<const float4*>(g_Xp);

    float4 acc = make_float4(0.f, 0.f, 0.f, 0.f);
    int i = beg;
    // 4-way unrolled gather for MLP
    for (; i + 4 <= end; i += 4) {
        int s0 = __ldg(&g_src_by_e[i + 0]);
        int s1 = __ldg(&g_src_by_e[i + 1]);
        int s2 = __ldg(&g_src_by_e[i + 2]);
        int s3 = __ldg(&g_src_by_e[i + 3]);
        float4 v0 = Xp4[(size_t)s0 * 32 + lane];
        float4 v1 = Xp4[(size_t)s1 * 32 + lane];
        float4 v2 = Xp4[(size_t)s2 * 32 + lane];
        float4 v3 = Xp4[(size_t)s3 * 32 + lane];
        acc.x += v0.x + v1.x + v2.x + v3.x;
        acc.y += v0.y + v1.y + v2.y + v3.y;
        acc.z += v0.z + v1.z + v2.z + v3.z;
        acc.w += v0.w + v1.w + v2.w + v3.w;
    }
    for (; i < end; i++) {
        int s = __ldg(&g_src_by_e[i]);
        float4 v = Xp4[(size_t)s * 32 + lane];
        acc.x += v.x; acc.y += v.y; acc.z += v.z; acc.w += v.w;
    }

    float sc = degE[e] * Wbuf[e];
    acc.x *= sc; acc.y *= sc; acc.z *= sc; acc.w *= sc;
    reinterpret_cast<float4*>(g_Xe)[(size_t)e * 32 + lane] = acc;
}

// ---------------------------------------------------------------------------
// Stage 2 (atomic-free): warp per node.
// out[v] = (sum_{e ni v} Xe[e]) * degV[v]
// ---------------------------------------------------------------------------
__global__ __launch_bounds__(256) void seg2_kernel(const float* __restrict__ degV,
                                                   float* __restrict__ out) {
    int gid  = blockIdx.x * blockDim.x + threadIdx.x;
    int v    = gid >> 5;
    int lane = gid & 31;
    if (v >= N_NODES) return;

    int beg = g_rowptr_v[v];
    int end = g_rowptr_v[v + 1];
    const float4* Xe4 = reinterpret_cast<const float4*>(g_Xe);

    float4 acc = make_float4(0.f, 0.f, 0.f, 0.f);
    int i = beg;
    for (; i + 4 <= end; i += 4) {
        int d0 = __ldg(&g_dst_by_v[i + 0]);
        int d1 = __ldg(&g_dst_by_v[i + 1]);
        int d2 = __ldg(&g_dst_by_v[i + 2]);
        int d3 = __ldg(&g_dst_by_v[i + 3]);
        float4 v0 = Xe4[(size_t)d0 * 32 + lane];
        float4 v1 = Xe4[(size_t)d1 * 32 + lane];
        float4 v2 = Xe4[(size_t)d2 * 32 + lane];
        float4 v3 = Xe4[(size_t)d3 * 32 + lane];
        acc.x += v0.x + v1.x + v2.x + v3.x;
        acc.y += v0.y + v1.y + v2.y + v3.y;
        acc.z += v0.z + v1.z + v2.z + v3.z;
        acc.w += v0.w + v1.w + v2.w + v3.w;
    }
    for (; i < end; i++) {
        int d = __ldg(&g_dst_by_v[i]);
        float4 vv = Xe4[(size_t)d * 32 + lane];
        acc.x += vv.x; acc.y += vv.y; acc.z += vv.z; acc.w += vv.w;
    }

    float sc = degV[v];
    acc.x *= sc; acc.y *= sc; acc.z *= sc; acc.w *= sc;
    reinterpret_cast<float4*>(out)[(size_t)v * 32 + lane] = acc;
}

// ---------------------------------------------------------------------------
// Launch
// ---------------------------------------------------------------------------
extern "C" void kernel_launch(void* const* d_in, const int* in_sizes, int n_in,
                              void* d_out, int out_size) {
    const float* X    = (const float*)d_in[0];
    const float* Wlin = (const float*)d_in[1];
    const float* degE = (const float*)d_in[2];
    const float* degV = (const float*)d_in[3];
    const float* Wbuf = (const float*)d_in[4];
    const int*   src  = (const int*)d_in[5];
    const int*   dst  = (const int*)d_in[6];
    float*       out  = (float*)d_out;

    // Resolve device-global addresses (host side; cheap, capturable-safe)
    int *p_cnt_e, *p_cnt_v, *p_rowptr_e, *p_rowptr_v, *p_cur_e, *p_cur_v;
    int *p_bsum_e, *p_bsum_v;
    cudaGetSymbolAddress((void**)&p_cnt_e,    g_cnt_e);
    cudaGetSymbolAddress((void**)&p_cnt_v,    g_cnt_v);
    cudaGetSymbolAddress((void**)&p_rowptr_e, g_rowptr_e);
    cudaGetSymbolAddress((void**)&p_rowptr_v, g_rowptr_v);
    cudaGetSymbolAddress((void**)&p_cur_e,    g_cur_e);
    cudaGetSymbolAddress((void**)&p_cur_v,    g_cur_v);
    cudaGetSymbolAddress((void**)&p_bsum_e,   g_bsum_e);
    cudaGetSymbolAddress((void**)&p_bsum_v,   g_bsum_v);

    const int nbE = (N_HEDGES + 1023) / 1024;   // 25
    const int nbV = (N_NODES  + 1023) / 1024;   // 98

    // 1. zero counters (memset is graph-capturable)
    cudaMemsetAsync(p_cnt_e, 0, N_HEDGES * sizeof(int));
    cudaMemsetAsync(p_cnt_v, 0, N_NODES  * sizeof(int));

    // 2. histogram
    hist_kernel<<<(NNZ + 255) / 256, 256>>>(src, dst);

    // 3. scans -> rowptr + cursors
    reduce_kernel<<<nbE, 1024>>>(p_cnt_e, N_HEDGES, p_bsum_e);
    reduce_kernel<<<nbV, 1024>>>(p_cnt_v, N_NODES,  p_bsum_v);
    scan_bsum_kernel<<<1, 1024>>>(p_bsum_e, nbE, p_rowptr_e + N_HEDGES);
    scan_bsum_kernel<<<1, 1024>>>(p_bsum_v, nbV, p_rowptr_v + N_NODES);
    scan_final_kernel<<<nbE, 1024>>>(p_cnt_e, N_HEDGES, p_bsum_e, p_rowptr_e, p_cur_e);
    scan_final_kernel<<<nbV, 1024>>>(p_cnt_v, N_NODES,  p_bsum_v, p_rowptr_v, p_cur_v);

    // 4. place edges into both CSRs
    place_kernel<<<(NNZ + 255) / 256, 256>>>(src, dst);

    // 5. GEMM (independent of CSR build; ordered in-stream)
    gemm_kernel<<<(N_NODES + 127) / 128, 256>>>(X, Wlin);

    // 6. stage 1: node -> hyperedge (atomic-free)
    seg1_kernel<<<(N_HEDGES * 32 + 255) / 256, 256>>>(degE, Wbuf);

    // 7. stage 2: hyperedge -> node (atomic-free, writes every out row)
    seg2_kernel<<<(N_NODES * 32 + 255) / 256, 256>>>(degV, out);
}

// round 3
// speedup vs baseline: 2.3816x; 1.3228x over previous
#include <cuda_runtime.h>
#include <cstdint>

#define N_NODES  100000
#define N_HEDGES 25000
#define NNZ      1600000
#define CH       128

// ---------------------------------------------------------------------------
// Device-global scratch
// ---------------------------------------------------------------------------
__device__ float g_Y[(size_t)N_HEDGES * CH];   // (degE*W) ⊙ (S1 X)   (12.8 MB)
__device__ float g_Z[(size_t)N_HEDGES * CH];   // g_Y @ Wlin          (12.8 MB)

__device__ int g_cnt_e[N_HEDGES];
__device__ int g_cnt_v[N_NODES];
__device__ int g_rowptr_e[N_HEDGES + 1];
__device__ int g_rowptr_v[N_NODES + 1];
__device__ int g_cur_e[N_HEDGES];
__device__ int g_cur_v[N_NODES];
__device__ int g_src_by_e[NNZ];   // src node per CSR(dst) slot
__device__ int g_dst_by_v[NNZ];   // dst hedge per CSR(src) slot
__device__ int g_bsum_e[128];
__device__ int g_bsum_v[128];

#define NB_E ((N_HEDGES + 1023) / 1024)   // 25
#define NB_V ((N_NODES  + 1023) / 1024)   // 98

// ---------------------------------------------------------------------------
// CSR build: histogram over both index arrays
// ---------------------------------------------------------------------------
__global__ void hist_kernel(const int* __restrict__ src, const int* __restrict__ dst) {
    int i = blockIdx.x * blockDim.x + threadIdx.x;
    if (i >= NNZ) return;
    atomicAdd(&g_cnt_e[dst[i]], 1);
    atomicAdd(&g_cnt_v[src[i]], 1);
}

// Merged per-block reduction: blocks [0,NB_E) -> E counters, [NB_E, NB_E+NB_V) -> V
__global__ void reduce_kernel() {
    __shared__ int s[1024];
    int tid = threadIdx.x;
    bool isE = blockIdx.x < NB_E;
    int b = isE ? blockIdx.x : blockIdx.x - NB_E;
    const int* cnt = isE ? g_cnt_e : g_cnt_v;
    int n = isE ? N_HEDGES : N_NODES;
    int i = b * 1024 + tid;
    s[tid] = (i < n) ? cnt[i] : 0;
    __syncthreads();
#pragma unroll
    for (int o = 512; o > 0; o >>= 1) {
        if (tid < o) s[tid] += s[tid + o];
        __syncthreads();
    }
    if (tid == 0) (isE ? g_bsum_e : g_bsum_v)[b] = s[0];
}

// Merged single-block scans: block 0 -> bsum_e, block 1 -> bsum_v
__global__ void scan_bsum_kernel() {
    __shared__ int s[1024];
    int tid = threadIdx.x;
    bool isE = blockIdx.x == 0;
    int* bsum = isE ? g_bsum_e : g_bsum_v;
    int nb = isE ? NB_E : NB_V;
    int v0 = (tid < nb) ? bsum[tid] : 0;
    s[tid] = v0;
    __syncthreads();
#pragma unroll
    for (int o = 1; o < 1024; o <<= 1) {
        int v = (tid >= o) ? s[tid - o] : 0;
        __syncthreads();
        s[tid] += v;
        __syncthreads();
    }
    if (tid < nb) bsum[tid] = s[tid] - v0;                       // exclusive
    if (tid == nb - 1) {
        if (isE) g_rowptr_e[N_HEDGES] = s[tid];
        else     g_rowptr_v[N_NODES]  = s[tid];
    }
}

// Merged final scan: per-block exclusive scan + block offset -> rowptr & cursor
__global__ void scan_final_kernel() {
    __shared__ int s[1024];
    int tid = threadIdx.x;
    bool isE = blockIdx.x < NB_E;
    int b = isE ? blockIdx.x : blockIdx.x - NB_E;
    const int* cnt  = isE ? g_cnt_e : g_cnt_v;
    const int* boff = isE ? g_bsum_e : g_bsum_v;
    int* rowptr     = isE ? g_rowptr_e : g_rowptr_v;
    int* cur        = isE ? g_cur_e : g_cur_v;
    int n = isE ? N_HEDGES : N_NODES;
    int i = b * 1024 + tid;
    int v0 = (i < n) ? cnt[i] : 0;
    s[tid] = v0;
    __syncthreads();
#pragma unroll
    for (int o = 1; o < 1024; o <<= 1) {
        int v = (tid >= o) ? s[tid - o] : 0;
        __syncthreads();
        s[tid] += v;
        __syncthreads();
    }
    if (i < n) {
        int val = s[tid] - v0 + boff[b];
        rowptr[i] = val;
        cur[i]    = val;
    }
}

// Place edges into both CSRs
__global__ void place_kernel(const int* __restrict__ src, const int* __restrict__ dst) {
    int i = blockIdx.x * blockDim.x + threadIdx.x;
    if (i >= NNZ) return;
    int s = src[i];
    int d = dst[i];
    int p = atomicAdd(&g_cur_e[d], 1);
    g_src_by_e[p] = s;
    int q = atomicAdd(&g_cur_v[s], 1);
    g_dst_by_v[q] = d;
}

// ---------------------------------------------------------------------------
// Stage 1 (atomic-free): warp per hyperedge, gathers RAW X.
// Y[e] = (sum_{v in e} X[v]) * degE[e] * W[e]
// ---------------------------------------------------------------------------
__global__ __launch_bounds__(256) void seg1_kernel(const float* __restrict__ X,
                                                   const float* __restrict__ degE,
                                                   const float* __restrict__ Wbuf) {
    int gid  = blockIdx.x * blockDim.x + threadIdx.x;
    int e    = gid >> 5;
    int lane = gid & 31;
    if (e >= N_HEDGES) return;

    int beg = g_rowptr_e[e];
    int end = g_rowptr_e[e + 1];
    const float4* X4 = reinterpret_cast<const float4*>(X);

    float4 acc = make_float4(0.f, 0.f, 0.f, 0.f);
    int i = beg;
    for (; i + 4 <= end; i += 4) {
        int s0 = __ldg(&g_src_by_e[i + 0]);
        int s1 = __ldg(&g_src_by_e[i + 1]);
        int s2 = __ldg(&g_src_by_e[i + 2]);
        int s3 = __ldg(&g_src_by_e[i + 3]);
        float4 v0 = __ldg(&X4[(size_t)s0 * 32 + lane]);
        float4 v1 = __ldg(&X4[(size_t)s1 * 32 + lane]);
        float4 v2 = __ldg(&X4[(size_t)s2 * 32 + lane]);
        float4 v3 = __ldg(&X4[(size_t)s3 * 32 + lane]);
        acc.x += v0.x + v1.x + v2.x + v3.x;
        acc.y += v0.y + v1.y + v2.y + v3.y;
        acc.z += v0.z + v1.z + v2.z + v3.z;
        acc.w += v0.w + v1.w + v2.w + v3.w;
    }
    for (; i < end; i++) {
        int s = __ldg(&g_src_by_e[i]);
        float4 v = __ldg(&X4[(size_t)s * 32 + lane]);
        acc.x += v.x; acc.y += v.y; acc.z += v.z; acc.w += v.w;
    }

    float sc = degE[e] * Wbuf[e];
    acc.x *= sc; acc.y *= sc; acc.z *= sc; acc.w *= sc;
    reinterpret_cast<float4*>(g_Y)[(size_t)e * 32 + lane] = acc;
}

// ---------------------------------------------------------------------------
// GEMM: g_Z = g_Y[25000,128] @ Wlin[128,128]
// 128x128 block tile, 256 threads, 8x8 register tile, BK=16
// ---------------------------------------------------------------------------
__global__ __launch_bounds__(256) void gemm_kernel(const float* __restrict__ W) {
    __shared__ float Xs[128][17];
    __shared__ float Ws[16][128];

    const int tid  = threadIdx.x;
    const int tx   = tid & 15;
    const int ty   = tid >> 4;
    const int row0 = blockIdx.x * 128;
    const float* A = g_Y;

    float acc[8][8];
#pragma unroll
    for (int i = 0; i < 8; i++)
#pragma unroll
        for (int j = 0; j < 8; j++) acc[i][j] = 0.f;

    for (int kk = 0; kk < CH; kk += 16) {
#pragma unroll
        for (int i = 0; i < 2; i++) {
            int t  = tid + i * 256;
            int r  = t >> 2;
            int c4 = (t & 3) * 4;
            float4 xv = make_float4(0.f, 0.f, 0.f, 0.f);
            if (row0 + r < N_HEDGES)
                xv = *reinterpret_cast<const float4*>(A + (size_t)(row0 + r) * CH + kk + c4);
            Xs[r][c4 + 0] = xv.x; Xs[r][c4 + 1] = xv.y;
            Xs[r][c4 + 2] = xv.z; Xs[r][c4 + 3] = xv.w;
        }
#pragma unroll
        for (int i = 0; i < 2; i++) {
            int t  = tid + i * 256;
            int wr = t >> 5;
            int wc = (t & 31) * 4;
            *reinterpret_cast<float4*>(&Ws[wr][wc]) =
                *reinterpret_cast<const float4*>(W + (size_t)(kk + wr) * CH + wc);
        }
        __syncthreads();

#pragma unroll
        for (int k = 0; k < 16; k++) {
            float a[8];
#pragma unroll
            for (int i = 0; i < 8; i++) a[i] = Xs[ty * 8 + i][k];
            float b[8];
            *reinterpret_cast<float4*>(&b[0]) = *reinterpret_cast<float4*>(&Ws[k][tx * 8]);
            *reinterpret_cast<float4*>(&b[4]) = *reinterpret_cast<float4*>(&Ws[k][tx * 8 + 4]);
#pragma unroll
            for (int i = 0; i < 8; i++)
#pragma unroll
                for (int j = 0; j < 8; j++) acc[i][j] += a[i] * b[j];
        }
        __syncthreads();
    }

#pragma unroll
    for (int i = 0; i < 8; i++) {
        int row = row0 + ty * 8 + i;
        if (row < N_HEDGES) {
            float* o = g_Z + (size_t)row * CH + tx * 8;
            *reinterpret_cast<float4*>(o)     = make_float4(acc[i][0], acc[i][1], acc[i][2], acc[i][3]);
            *reinterpret_cast<float4*>(o + 4) = make_float4(acc[i][4], acc[i][5], acc[i][6], acc[i][7]);
        }
    }
}

// ---------------------------------------------------------------------------
// Stage 2 (atomic-free): warp per node.
// out[v] = (sum_{e ni v} Z[e]) * degV[v]
// ---------------------------------------------------------------------------
__global__ __launch_bounds__(256) void seg2_kernel(const float* __restrict__ degV,
                                                   float* __restrict__ out) {
    int gid  = blockIdx.x * blockDim.x + threadIdx.x;
    int v    = gid >> 5;
    int lane = gid & 31;
    if (v >= N_NODES) return;

    int beg = g_rowptr_v[v];
    int end = g_rowptr_v[v + 1];
    const float4* Z4 = reinterpret_cast<const float4*>(g_Z);

    float4 acc = make_float4(0.f, 0.f, 0.f, 0.f);
    int i = beg;
    for (; i + 4 <= end; i += 4) {
        int d0 = __ldg(&g_dst_by_v[i + 0]);
        int d1 = __ldg(&g_dst_by_v[i + 1]);
        int d2 = __ldg(&g_dst_by_v[i + 2]);
        int d3 = __ldg(&g_dst_by_v[i + 3]);
        float4 v0 = __ldg(&Z4[(size_t)d0 * 32 + lane]);
        float4 v1 = __ldg(&Z4[(size_t)d1 * 32 + lane]);
        float4 v2 = __ldg(&Z4[(size_t)d2 * 32 + lane]);
        float4 v3 = __ldg(&Z4[(size_t)d3 * 32 + lane]);
        acc.x += v0.x + v1.x + v2.x + v3.x;
        acc.y += v0.y + v1.y + v2.y + v3.y;
        acc.z += v0.z + v1.z + v2.z + v3.z;
        acc.w += v0.w + v1.w + v2.w + v3.w;
    }
    for (; i < end; i++) {
        int d = __ldg(&g_dst_by_v[i]);
        float4 vv = __ldg(&Z4[(size_t)d * 32 + lane]);
        acc.x += vv.x; acc.y += vv.y; acc.z += vv.z; acc.w += vv.w;
    }

    float sc = degV[v];
    acc.x *= sc; acc.y *= sc; acc.z *= sc; acc.w *= sc;
    reinterpret_cast<float4*>(out)[(size_t)v * 32 + lane] = acc;
}

// ---------------------------------------------------------------------------
// Launch
// ---------------------------------------------------------------------------
extern "C" void kernel_launch(void* const* d_in, const int* in_sizes, int n_in,
                              void* d_out, int out_size) {
    const float* X    = (const float*)d_in[0];
    const float* Wlin = (const float*)d_in[1];
    const float* degE = (const float*)d_in[2];
    const float* degV = (const float*)d_in[3];
    const float* Wbuf = (const float*)d_in[4];
    const int*   src  = (const int*)d_in[5];
    const int*   dst  = (const int*)d_in[6];
    float*       out  = (float*)d_out;

    int *p_cnt_e, *p_cnt_v;
    cudaGetSymbolAddress((void**)&p_cnt_e, g_cnt_e);
    cudaGetSymbolAddress((void**)&p_cnt_v, g_cnt_v);

    // 1. zero counters
    cudaMemsetAsync(p_cnt_e, 0, N_HEDGES * sizeof(int));
    cudaMemsetAsync(p_cnt_v, 0, N_NODES  * sizeof(int));

    // 2. histogram
    hist_kernel<<<(NNZ + 255) / 256, 256>>>(src, dst);

    // 3. scans (E and V merged per launch)
    reduce_kernel<<<NB_E + NB_V, 1024>>>();
    scan_bsum_kernel<<<2, 1024>>>();
    scan_final_kernel<<<NB_E + NB_V, 1024>>>();

    // 4. place edges into both CSRs
    place_kernel<<<(NNZ + 255) / 256, 256>>>(src, dst);

    // 5. stage 1: node -> hyperedge on RAW X (atomic-free)
    seg1_kernel<<<(N_HEDGES * 32 + 255) / 256, 256>>>(X, degE, Wbuf);

    // 6. small GEMM at hyperedge level: Z = Y @ Wlin  (4x fewer FLOPs)
    gemm_kernel<<<(N_HEDGES + 127) / 128, 256>>>(Wlin);

    // 7. stage 2: hyperedge -> node (atomic-free, writes every out row)
    seg2_kernel<<<(N_NODES * 32 + 255) / 256, 256>>>(degV, out);
}

// round 4
// speedup vs baseline: 2.6220x; 1.1009x over previous
#include <cuda_runtime.h>
#include <cuda_fp16.h>
#include <cstdint>

#define N_NODES  100000
#define N_HEDGES 25000
#define NNZ      1600000
#define CH       128

// ---------------------------------------------------------------------------
// Device-global scratch
// ---------------------------------------------------------------------------
__device__ __half g_Xh[(size_t)N_NODES * CH];   // fp16 copy of X      (25.6 MB)
__device__ float  g_Y[(size_t)N_HEDGES * CH];   // (degE*W) ⊙ (S1 X)   (12.8 MB)
__device__ __half g_Zh[(size_t)N_HEDGES * CH];  // fp16(Y @ Wlin)      ( 6.4 MB)

__device__ int g_cnt_e[N_HEDGES];
__device__ int g_cnt_v[N_NODES];
__device__ int g_rowptr_e[N_HEDGES + 1];
__device__ int g_rowptr_v[N_NODES + 1];
__device__ int g_cur_e[N_HEDGES];
__device__ int g_cur_v[N_NODES];
__device__ int g_src_by_e[NNZ];
__device__ int g_dst_by_v[NNZ];
__device__ int g_bsum_e[128];
__device__ int g_bsum_v[128];

#define NB_E ((N_HEDGES + 1023) / 1024)   // 25
#define NB_V ((N_NODES  + 1023) / 1024)   // 98

// ---------------------------------------------------------------------------
// X -> fp16 conversion (8 elems / thread)
// ---------------------------------------------------------------------------
__global__ __launch_bounds__(256) void convert_kernel(const float* __restrict__ X) {
    size_t i = ((size_t)blockIdx.x * blockDim.x + threadIdx.x) * 8;
    if (i >= (size_t)N_NODES * CH) return;
    float4 a = *reinterpret_cast<const float4*>(X + i);
    float4 b = *reinterpret_cast<const float4*>(X + i + 4);
    __half2 h[4];
    h[0] = __floats2half2_rn(a.x, a.y);
    h[1] = __floats2half2_rn(a.z, a.w);
    h[2] = __floats2half2_rn(b.x, b.y);
    h[3] = __floats2half2_rn(b.z, b.w);
    *reinterpret_cast<uint4*>(g_Xh + i) = *reinterpret_cast<uint4*>(h);
}

// ---------------------------------------------------------------------------
// CSR build
// ---------------------------------------------------------------------------
__global__ void hist_kernel(const int* __restrict__ src, const int* __restrict__ dst) {
    int i = blockIdx.x * blockDim.x + threadIdx.x;
    if (i >= NNZ) return;
    atomicAdd(&g_cnt_e[dst[i]], 1);
    atomicAdd(&g_cnt_v[src[i]], 1);
}

__global__ void reduce_kernel() {
    __shared__ int s[1024];
    int tid = threadIdx.x;
    bool isE = blockIdx.x < NB_E;
    int b = isE ? blockIdx.x : blockIdx.x - NB_E;
    const int* cnt = isE ? g_cnt_e : g_cnt_v;
    int n = isE ? N_HEDGES : N_NODES;
    int i = b * 1024 + tid;
    s[tid] = (i < n) ? cnt[i] : 0;
    __syncthreads();
#pragma unroll
    for (int o = 512; o > 0; o >>= 1) {
        if (tid < o) s[tid] += s[tid + o];
        __syncthreads();
    }
    if (tid == 0) (isE ? g_bsum_e : g_bsum_v)[b] = s[0];
}

__global__ void scan_bsum_kernel() {
    __shared__ int s[1024];
    int tid = threadIdx.x;
    bool isE = blockIdx.x == 0;
    int* bsum = isE ? g_bsum_e : g_bsum_v;
    int nb = isE ? NB_E : NB_V;
    int v0 = (tid < nb) ? bsum[tid] : 0;
    s[tid] = v0;
    __syncthreads();
#pragma unroll
    for (int o = 1; o < 1024; o <<= 1) {
        int v = (tid >= o) ? s[tid - o] : 0;
        __syncthreads();
        s[tid] += v;
        __syncthreads();
    }
    if (tid < nb) bsum[tid] = s[tid] - v0;
    if (tid == nb - 1) {
        if (isE) g_rowptr_e[N_HEDGES] = s[tid];
        else     g_rowptr_v[N_NODES]  = s[tid];
    }
}

__global__ void scan_final_kernel() {
    __shared__ int s[1024];
    int tid = threadIdx.x;
    bool isE = blockIdx.x < NB_E;
    int b = isE ? blockIdx.x : blockIdx.x - NB_E;
    const int* cnt  = isE ? g_cnt_e : g_cnt_v;
    const int* boff = isE ? g_bsum_e : g_bsum_v;
    int* rowptr     = isE ? g_rowptr_e : g_rowptr_v;
    int* cur        = isE ? g_cur_e : g_cur_v;
    int n = isE ? N_HEDGES : N_NODES;
    int i = b * 1024 + tid;
    int v0 = (i < n) ? cnt[i] : 0;
    s[tid] = v0;
    __syncthreads();
#pragma unroll
    for (int o = 1; o < 1024; o <<= 1) {
        int v = (tid >= o) ? s[tid - o] : 0;
        __syncthreads();
        s[tid] += v;
        __syncthreads();
    }
    if (i < n) {
        int val = s[tid] - v0 + boff[b];
        rowptr[i] = val;
        cur[i]    = val;
    }
}

__global__ void place_kernel(const int* __restrict__ src, const int* __restrict__ dst) {
    int i = blockIdx.x * blockDim.x + threadIdx.x;
    if (i >= NNZ) return;
    int s = src[i];
    int d = dst[i];
    int p = atomicAdd(&g_cur_e[d], 1);
    g_src_by_e[p] = s;
    int q = atomicAdd(&g_cur_v[s], 1);
    g_dst_by_v[q] = d;
}

// ---------------------------------------------------------------------------
// Stage 1: warp per hyperedge, gathers fp16 Xh, accumulates fp32.
// Y[e] = (sum_{v in e} X[v]) * degE[e] * W[e]
// Lane covers channels [lane*4, lane*4+4): one uint2 (4 halfs) per row.
// ---------------------------------------------------------------------------
__global__ __launch_bounds__(256) void seg1_kernel(const float* __restrict__ degE,
                                                   const float* __restrict__ Wbuf) {
    int gid  = blockIdx.x * blockDim.x + threadIdx.x;
    int e    = gid >> 5;
    int lane = gid & 31;
    if (e >= N_HEDGES) return;

    int beg = g_rowptr_e[e];
    int end = g_rowptr_e[e + 1];
    const uint2* Xh2 = reinterpret_cast<const uint2*>(g_Xh);

    float4 acc = make_float4(0.f, 0.f, 0.f, 0.f);
    int i = beg;
    for (; i + 4 <= end; i += 4) {
        int s0 = __ldg(&g_src_by_e[i + 0]);
        int s1 = __ldg(&g_src_by_e[i + 1]);
        int s2 = __ldg(&g_src_by_e[i + 2]);
        int s3 = __ldg(&g_src_by_e[i + 3]);
        uint2 u0 = __ldg(&Xh2[(size_t)s0 * 32 + lane]);
        uint2 u1 = __ldg(&Xh2[(size_t)s1 * 32 + lane]);
        uint2 u2 = __ldg(&Xh2[(size_t)s2 * 32 + lane]);
        uint2 u3 = __ldg(&Xh2[(size_t)s3 * 32 + lane]);
#pragma unroll
        for (int j = 0; j < 4; j++) {
            uint2 u = (j == 0) ? u0 : (j == 1) ? u1 : (j == 2) ? u2 : u3;
            float2 lo = __half22float2(*reinterpret_cast<__half2*>(&u.x));
            float2 hi = __half22float2(*reinterpret_cast<__half2*>(&u.y));
            acc.x += lo.x; acc.y += lo.y; acc.z += hi.x; acc.w += hi.y;
        }
    }
    for (; i < end; i++) {
        int s = __ldg(&g_src_by_e[i]);
        uint2 u = __ldg(&Xh2[(size_t)s * 32 + lane]);
        float2 lo = __half22float2(*reinterpret_cast<__half2*>(&u.x));
        float2 hi = __half22float2(*reinterpret_cast<__half2*>(&u.y));
        acc.x += lo.x; acc.y += lo.y; acc.z += hi.x; acc.w += hi.y;
    }

    float sc = degE[e] * Wbuf[e];
    acc.x *= sc; acc.y *= sc; acc.z *= sc; acc.w *= sc;
    reinterpret_cast<float4*>(g_Y)[(size_t)e * 32 + lane] = acc;  // channels lane*4..+3
}

// ---------------------------------------------------------------------------
// GEMM: g_Zh = fp16( g_Y[25000,128] @ Wlin[128,128] )
// ---------------------------------------------------------------------------
__global__ __launch_bounds__(256) void gemm_kernel(const float* __restrict__ W) {
    __shared__ float Xs[128][17];
    __shared__ float Ws[16][128];

    const int tid  = threadIdx.x;
    const int tx   = tid & 15;
    const int ty   = tid >> 4;
    const int row0 = blockIdx.x * 128;
    const float* A = g_Y;

    float acc[8][8];
#pragma unroll
    for (int i = 0; i < 8; i++)
#pragma unroll
        for (int j = 0; j < 8; j++) acc[i][j] = 0.f;

    for (int kk = 0; kk < CH; kk += 16) {
#pragma unroll
        for (int i = 0; i < 2; i++) {
            int t  = tid + i * 256;
            int r  = t >> 2;
            int c4 = (t & 3) * 4;
            float4 xv = make_float4(0.f, 0.f, 0.f, 0.f);
            if (row0 + r < N_HEDGES)
                xv = *reinterpret_cast<const float4*>(A + (size_t)(row0 + r) * CH + kk + c4);
            Xs[r][c4 + 0] = xv.x; Xs[r][c4 + 1] = xv.y;
            Xs[r][c4 + 2] = xv.z; Xs[r][c4 + 3] = xv.w;
        }
#pragma unroll
        for (int i = 0; i < 2; i++) {
            int t  = tid + i * 256;
            int wr = t >> 5;
            int wc = (t & 31) * 4;
            *reinterpret_cast<float4*>(&Ws[wr][wc]) =
                *reinterpret_cast<const float4*>(W + (size_t)(kk + wr) * CH + wc);
        }
        __syncthreads();

#pragma unroll
        for (int k = 0; k < 16; k++) {
            float a[8];
#pragma unroll
            for (int i = 0; i < 8; i++) a[i] = Xs[ty * 8 + i][k];
            float b[8];
            *reinterpret_cast<float4*>(&b[0]) = *reinterpret_cast<float4*>(&Ws[k][tx * 8]);
            *reinterpret_cast<float4*>(&b[4]) = *reinterpret_cast<float4*>(&Ws[k][tx * 8 + 4]);
#pragma unroll
            for (int i = 0; i < 8; i++)
#pragma unroll
                for (int j = 0; j < 8; j++) acc[i][j] += a[i] * b[j];
        }
        __syncthreads();
    }

#pragma unroll
    for (int i = 0; i < 8; i++) {
        int row = row0 + ty * 8 + i;
        if (row < N_HEDGES) {
            __half2 h[4];
            h[0] = __floats2half2_rn(acc[i][0], acc[i][1]);
            h[1] = __floats2half2_rn(acc[i][2], acc[i][3]);
            h[2] = __floats2half2_rn(acc[i][4], acc[i][5]);
            h[3] = __floats2half2_rn(acc[i][6], acc[i][7]);
            *reinterpret_cast<uint4*>(g_Zh + (size_t)row * CH + tx * 8) =
                *reinterpret_cast<uint4*>(h);
        }
    }
}

// ---------------------------------------------------------------------------
// Stage 2: warp per node, gathers fp16 Zh, accumulates fp32.
// out[v] = (sum_{e ni v} Z[e]) * degV[v]
// ---------------------------------------------------------------------------
__global__ __launch_bounds__(256) void seg2_kernel(const float* __restrict__ degV,
                                                   float* __restrict__ out) {
    int gid  = blockIdx.x * blockDim.x + threadIdx.x;
    int v    = gid >> 5;
    int lane = gid & 31;
    if (v >= N_NODES) return;

    int beg = g_rowptr_v[v];
    int end = g_rowptr_v[v + 1];
    const uint2* Zh2 = reinterpret_cast<const uint2*>(g_Zh);

    float4 acc = make_float4(0.f, 0.f, 0.f, 0.f);
    int i = beg;
    for (; i + 4 <= end; i += 4) {
        int d0 = __ldg(&g_dst_by_v[i + 0]);
        int d1 = __ldg(&g_dst_by_v[i + 1]);
        int d2 = __ldg(&g_dst_by_v[i + 2]);
        int d3 = __ldg(&g_dst_by_v[i + 3]);
        uint2 u0 = __ldg(&Zh2[(size_t)d0 * 32 + lane]);
        uint2 u1 = __ldg(&Zh2[(size_t)d1 * 32 + lane]);
        uint2 u2 = __ldg(&Zh2[(size_t)d2 * 32 + lane]);
        uint2 u3 = __ldg(&Zh2[(size_t)d3 * 32 + lane]);
#pragma unroll
        for (int j = 0; j < 4; j++) {
            uint2 u = (j == 0) ? u0 : (j == 1) ? u1 : (j == 2) ? u2 : u3;
            float2 lo = __half22float2(*reinterpret_cast<__half2*>(&u.x));
            float2 hi = __half22float2(*reinterpret_cast<__half2*>(&u.y));
            acc.x += lo.x; acc.y += lo.y; acc.z += hi.x; acc.w += hi.y;
        }
    }
    for (; i < end; i++) {
        int d = __ldg(&g_dst_by_v[i]);
        uint2 u = __ldg(&Zh2[(size_t)d * 32 + lane]);
        float2 lo = __half22float2(*reinterpret_cast<__half2*>(&u.x));
        float2 hi = __half22float2(*reinterpret_cast<__half2*>(&u.y));
        acc.x += lo.x; acc.y += lo.y; acc.z += hi.x; acc.w += hi.y;
    }

    float sc = degV[v];
    acc.x *= sc; acc.y *= sc; acc.z *= sc; acc.w *= sc;
    reinterpret_cast<float4*>(out)[(size_t)v * 32 + lane] = acc;
}

// ---------------------------------------------------------------------------
// Launch
// ---------------------------------------------------------------------------
extern "C" void kernel_launch(void* const* d_in, const int* in_sizes, int n_in,
                              void* d_out, int out_size) {
    const float* X    = (const float*)d_in[0];
    const float* Wlin = (const float*)d_in[1];
    const float* degE = (const float*)d_in[2];
    const float* degV = (const float*)d_in[3];
    const float* Wbuf = (const float*)d_in[4];
    const int*   src  = (const int*)d_in[5];
    const int*   dst  = (const int*)d_in[6];
    float*       out  = (float*)d_out;

    int *p_cnt_e, *p_cnt_v;
    cudaGetSymbolAddress((void**)&p_cnt_e, g_cnt_e);
    cudaGetSymbolAddress((void**)&p_cnt_v, g_cnt_v);

    // 1. zero counters
    cudaMemsetAsync(p_cnt_e, 0, N_HEDGES * sizeof(int));
    cudaMemsetAsync(p_cnt_v, 0, N_NODES  * sizeof(int));

    // 2. X -> fp16 (needed only by seg1; runs while CSR builds serially)
    convert_kernel<<<((size_t)N_NODES * CH / 8 + 255) / 256, 256>>>(X);

    // 3. histogram
    hist_kernel<<<(NNZ + 255) / 256, 256>>>(src, dst);

    // 4. scans
    reduce_kernel<<<NB_E + NB_V, 1024>>>();
    scan_bsum_kernel<<<2, 1024>>>();
    scan_final_kernel<<<NB_E + NB_V, 1024>>>();

    // 5. place edges
    place_kernel<<<(NNZ + 255) / 256, 256>>>(src, dst);

    // 6. stage 1: node -> hyperedge (fp16 gather, fp32 accumulate)
    seg1_kernel<<<(N_HEDGES * 32 + 255) / 256, 256>>>(degE, Wbuf);

    // 7. GEMM at hyperedge level, fp16 epilogue
    gemm_kernel<<<(N_HEDGES + 127) / 128, 256>>>(Wlin);

    // 8. stage 2: hyperedge -> node (fp16 gather, fp32 out)
    seg2_kernel<<<(N_NODES * 32 + 255) / 256, 256>>>(degV, out);
}

// round 5
// speedup vs baseline: 2.7696x; 1.0563x over previous
#include <cuda_runtime.h>
#include <cuda_fp16.h>
#include <cstdint>

#define N_NODES  100000
#define N_HEDGES 25000
#define NNZ      1600000
#define CH       128

#define NB_E ((N_HEDGES + 1023) / 1024)   // 25
#define NB_V ((N_NODES  + 1023) / 1024)   // 98
#define NBLK (NB_E + NB_V)                // 123

// ---------------------------------------------------------------------------
// Device-global scratch
// ---------------------------------------------------------------------------
__device__ __half g_Xh[(size_t)N_NODES * CH];   // fp16 X            (25.6 MB)
__device__ __half g_Wh[CH * CH];                // fp16 Wlin
__device__ __half g_Yh[(size_t)N_HEDGES * CH];  // fp16 seg1 output  ( 6.4 MB)
__device__ __half g_Zh[(size_t)N_HEDGES * CH];  // fp16 GEMM output  ( 6.4 MB)

__device__ int g_cnt_e[N_HEDGES];
__device__ int g_cnt_v[N_NODES];
__device__ int g_rowptr_e[N_HEDGES + 1];
__device__ int g_rowptr_v[N_NODES + 1];
__device__ int g_cur_e[N_HEDGES];
__device__ int g_cur_v[N_NODES];
__device__ int g_src_by_e[NNZ];
__device__ int g_dst_by_v[NNZ];
__device__ int g_part[128];     // per-block partial sums (scan)
__device__ int g_boff[128];     // per-block exclusive offsets (scan)
__device__ int g_sync[2];       // [0]=arrive counter, [1]=release flag

// ---------------------------------------------------------------------------
// fp32 -> fp16 converts
// ---------------------------------------------------------------------------
__global__ __launch_bounds__(256) void convertX_kernel(const float* __restrict__ X) {
    size_t i = ((size_t)blockIdx.x * blockDim.x + threadIdx.x) * 8;
    if (i >= (size_t)N_NODES * CH) return;
    float4 a = *reinterpret_cast<const float4*>(X + i);
    float4 b = *reinterpret_cast<const float4*>(X + i + 4);
    __half2 h[4];
    h[0] = __floats2half2_rn(a.x, a.y);
    h[1] = __floats2half2_rn(a.z, a.w);
    h[2] = __floats2half2_rn(b.x, b.y);
    h[3] = __floats2half2_rn(b.z, b.w);
    *reinterpret_cast<uint4*>(g_Xh + i) = *reinterpret_cast<uint4*>(h);
}

__global__ __launch_bounds__(256) void convertW_kernel(const float* __restrict__ W) {
    size_t i = ((size_t)blockIdx.x * blockDim.x + threadIdx.x) * 8;
    if (i >= (size_t)CH * CH) return;
    float4 a = *reinterpret_cast<const float4*>(W + i);
    float4 b = *reinterpret_cast<const float4*>(W + i + 4);
    __half2 h[4];
    h[0] = __floats2half2_rn(a.x, a.y);
    h[1] = __floats2half2_rn(a.z, a.w);
    h[2] = __floats2half2_rn(b.x, b.y);
    h[3] = __floats2half2_rn(b.z, b.w);
    *reinterpret_cast<uint4*>(g_Wh + i) = *reinterpret_cast<uint4*>(h);
}

// ---------------------------------------------------------------------------
// CSR build
// ---------------------------------------------------------------------------
__global__ void hist_kernel(const int* __restrict__ src, const int* __restrict__ dst) {
    int i = blockIdx.x * blockDim.x + threadIdx.x;
    if (i >= NNZ) return;
    atomicAdd(&g_cnt_e[dst[i]], 1);
    atomicAdd(&g_cnt_v[src[i]], 1);
}

// Single-pass scan over both counter arrays.
// 123 blocks of 1024 (all resident on 148 SMs -> global barrier is safe).
__global__ __launch_bounds__(1024) void scan_onepass_kernel() {
    __shared__ int s[1024];
    __shared__ int p[128];
    __shared__ int sh_flag;   // is-last-block
    __shared__ int sh_boff;

    const int tid = threadIdx.x;
    const int bid = blockIdx.x;
    const bool isE = bid < NB_E;
    const int b = isE ? bid : bid - NB_E;
    const int n = isE ? N_HEDGES : N_NODES;
    const int* cnt  = isE ? g_cnt_e : g_cnt_v;
    int* rowptr     = isE ? g_rowptr_e : g_rowptr_v;
    int* cur        = isE ? g_cur_e : g_cur_v;

    const int i = b * 1024 + tid;
    const int v0 = (i < n) ? cnt[i] : 0;

    // inclusive block scan
    s[tid] = v0;
    __syncthreads();
#pragma unroll
    for (int o = 1; o < 1024; o <<= 1) {
        int t = (tid >= o) ? s[tid - o] : 0;
        __syncthreads();
        s[tid] += t;
        __syncthreads();
    }

    // publish partial, arrive
    if (tid == 1023) {
        g_part[bid] = s[1023];
        __threadfence();
        int ticket = atomicAdd(&g_sync[0], 1);
        sh_flag = (ticket == NBLK - 1);
    }
    __syncthreads();

    if (sh_flag) {
        // last block: segmented exclusive scan of the 123 partials
        int mine = 0;
        if (tid < NBLK) {
            mine = atomicAdd(&g_part[tid], 0);   // L1-bypassing read
            p[tid] = mine;
        }
        __syncthreads();
#pragma unroll
        for (int o = 1; o < 128; o <<= 1) {
            int add = 0;
            if (tid < NBLK && tid >= o) {
                bool sameSeg = (tid < NB_E) == ((tid - o) < NB_E);
                if (sameSeg) add = p[tid - o];
            }
            __syncthreads();
            if (tid < NBLK) p[tid] += add;
            __syncthreads();
        }
        if (tid < NBLK) g_boff[tid] = p[tid] - mine;     // exclusive
        if (tid == NB_E - 1) g_rowptr_e[N_HEDGES] = p[tid];
        if (tid == NBLK - 1) g_rowptr_v[N_NODES]  = p[tid];
        __threadfence();
        if (tid == 0) atomicExch(&g_sync[1], 1);
    }

    // wait for release, fetch block offset
    if (tid == 0) {
        while (atomicAdd(&g_sync[1], 0) == 0) __nanosleep(64);
        sh_boff = atomicAdd(&g_boff[bid], 0);
    }
    __syncthreads();

    if (i < n) {
        int val = s[tid] - v0 + sh_boff;   // exclusive prefix + block offset
        rowptr[i] = val;
        cur[i]    = val;
    }
}

__global__ void place_kernel(const int* __restrict__ src, const int* __restrict__ dst) {
    int i = blockIdx.x * blockDim.x + threadIdx.x;
    if (i >= NNZ) return;
    int s = src[i];
    int d = dst[i];
    int pp = atomicAdd(&g_cur_e[d], 1);
    g_src_by_e[pp] = s;
    int q = atomicAdd(&g_cur_v[s], 1);
    g_dst_by_v[q] = d;
}

// ---------------------------------------------------------------------------
// Stage 1: warp per hyperedge; 16 lanes cover a row (uint4 = 8 halfs each),
// the two warp-halves process alternating edges; fp32 accumulate.
// Yh[e] = fp16( (sum_{v in e} X[v]) * degE[e]*W[e] )
// ---------------------------------------------------------------------------
__global__ __launch_bounds__(256) void seg1_kernel(const float* __restrict__ degE,
                                                   const float* __restrict__ Wbuf) {
    int gid  = blockIdx.x * blockDim.x + threadIdx.x;
    int e    = gid >> 5;
    int lane = gid & 31;
    if (e >= N_HEDGES) return;
    int half = lane >> 4;
    int sub  = lane & 15;

    int beg = g_rowptr_e[e];
    int end = g_rowptr_e[e + 1];
    const uint4* Xh4 = reinterpret_cast<const uint4*>(g_Xh);

    float acc[8];
#pragma unroll
    for (int j = 0; j < 8; j++) acc[j] = 0.f;

    int i = beg + half;
    for (; i + 6 < end; i += 8) {
        int s0 = __ldg(&g_src_by_e[i + 0]);
        int s1 = __ldg(&g_src_by_e[i + 2]);
        int s2 = __ldg(&g_src_by_e[i + 4]);
        int s3 = __ldg(&g_src_by_e[i + 6]);
        uint4 u0 = __ldg(&Xh4[(size_t)s0 * 16 + sub]);
        uint4 u1 = __ldg(&Xh4[(size_t)s1 * 16 + sub]);
        uint4 u2 = __ldg(&Xh4[(size_t)s2 * 16 + sub]);
        uint4 u3 = __ldg(&Xh4[(size_t)s3 * 16 + sub]);
#pragma unroll
        for (int j = 0; j < 4; j++) {
            uint4 u = (j == 0) ? u0 : (j == 1) ? u1 : (j == 2) ? u2 : u3;
            const __half2* h = reinterpret_cast<const __half2*>(&u);
#pragma unroll
            for (int q = 0; q < 4; q++) {
                float2 f = __half22float2(h[q]);
                acc[q * 2]     += f.x;
                acc[q * 2 + 1] += f.y;
            }
        }
    }
    for (; i < end; i += 2) {
        int s = __ldg(&g_src_by_e[i]);
        uint4 u = __ldg(&Xh4[(size_t)s * 16 + sub]);
        const __half2* h = reinterpret_cast<const __half2*>(&u);
#pragma unroll
        for (int q = 0; q < 4; q++) {
            float2 f = __half22float2(h[q]);
            acc[q * 2]     += f.x;
            acc[q * 2 + 1] += f.y;
        }
    }

    // merge halves
#pragma unroll
    for (int j = 0; j < 8; j++)
        acc[j] += __shfl_xor_sync(0xffffffffu, acc[j], 16);

    if (half == 0) {
        float sc = degE[e] * Wbuf[e];
        __half2 h[4];
#pragma unroll
        for (int q = 0; q < 4; q++)
            h[q] = __floats2half2_rn(acc[q * 2] * sc, acc[q * 2 + 1] * sc);
        *reinterpret_cast<uint4*>(g_Yh + (size_t)e * CH + sub * 8) =
            *reinterpret_cast<uint4*>(h);
    }
}

// ---------------------------------------------------------------------------
// HMMA GEMM: Zh[25000,128] = Yh @ Wh   (fp16 in, fp32 accum, fp16 out)
// Block: 128 rows, 256 threads (8 warps, 16 rows each). Full K=N=128.
// ---------------------------------------------------------------------------
#define GS 136   // smem stride in halfs (272 B -> conflict-free ldmatrix)

__global__ __launch_bounds__(256) void gemm_hmma_kernel() {
    extern __shared__ __half dsm[];
    __half* As = dsm;             // 128 x GS
    __half* Bs = dsm + 128 * GS;  // 128 x GS

    const int tid  = threadIdx.x;
    const int warp = tid >> 5;
    const int lane = tid & 31;
    const int row0 = blockIdx.x * 128;

    // load A tile (guarded) and B (= Wh) into smem
    for (int t = tid; t < 128 * 16; t += 256) {
        int r = t >> 4;
        int c = (t & 15) * 8;
        uint4 v = make_uint4(0, 0, 0, 0);
        if (row0 + r < N_HEDGES)
            v = *reinterpret_cast<const uint4*>(g_Yh + (size_t)(row0 + r) * CH + c);
        *reinterpret_cast<uint4*>(&As[r * GS + c]) = v;
        *reinterpret_cast<uint4*>(&Bs[r * GS + c]) =
            *reinterpret_cast<const uint4*>(g_Wh + (size_t)r * CH + c);
    }
    __syncthreads();

    const int m0 = warp * 16;
    float acc[16][4];
#pragma unroll
    for (int t = 0; t < 16; t++)
#pragma unroll
        for (int j = 0; j < 4; j++) acc[t][j] = 0.f;

#pragma unroll
    for (int k0 = 0; k0 < 128; k0 += 16) {
        uint32_t a[4];
        {
            uint32_t addr = (uint32_t)__cvta_generic_to_shared(
                &As[(m0 + (lane & 15)) * GS + k0 + (lane >> 4) * 8]);
            asm volatile("ldmatrix.sync.aligned.m8n8.x4.shared.b16 {%0,%1,%2,%3}, [%4];"
                         : "=r"(a[0]), "=r"(a[1]), "=r"(a[2]), "=r"(a[3]) : "r"(addr));
        }
#pragma unroll
        for (int n0 = 0; n0 < 128; n0 += 16) {
            uint32_t b[4];
            uint32_t addr = (uint32_t)__cvta_generic_to_shared(
                &Bs[(k0 + (lane & 15)) * GS + n0 + (lane >> 4) * 8]);
            asm volatile("ldmatrix.sync.aligned.m8n8.x4.trans.shared.b16 {%0,%1,%2,%3}, [%4];"
                         : "=r"(b[0]), "=r"(b[1]), "=r"(b[2]), "=r"(b[3]) : "r"(addr));
            int t0 = n0 >> 3;
            asm volatile("mma.sync.aligned.m16n8k16.row.col.f32.f16.f16.f32 "
                         "{%0,%1,%2,%3},{%4,%5,%6,%7},{%8,%9},{%0,%1,%2,%3};"
                         : "+f"(acc[t0][0]), "+f"(acc[t0][1]), "+f"(acc[t0][2]), "+f"(acc[t0][3])
                         : "r"(a[0]), "r"(a[1]), "r"(a[2]), "r"(a[3]), "r"(b[0]), "r"(b[1]));
            asm volatile("mma.sync.aligned.m16n8k16.row.col.f32.f16.f16.f32 "
                         "{%0,%1,%2,%3},{%4,%5,%6,%7},{%8,%9},{%0,%1,%2,%3};"
                         : "+f"(acc[t0+1][0]), "+f"(acc[t0+1][1]), "+f"(acc[t0+1][2]), "+f"(acc[t0+1][3])
                         : "r"(a[0]), "r"(a[1]), "r"(a[2]), "r"(a[3]), "r"(b[2]), "r"(b[3]));
        }
    }

    // epilogue: fp16 stores
    const int groupID = lane >> 2;
    const int tig     = lane & 3;
    const int rowA = row0 + m0 + groupID;
    const int rowB = rowA + 8;
#pragma unroll
    for (int t = 0; t < 16; t++) {
        int col = t * 8 + tig * 2;
        if (rowA < N_HEDGES)
            *reinterpret_cast<__half2*>(g_Zh + (size_t)rowA * CH + col) =
                __floats2half2_rn(acc[t][0], acc[t][1]);
        if (rowB < N_HEDGES)
            *reinterpret_cast<__half2*>(g_Zh + (size_t)rowB * CH + col) =
                __floats2half2_rn(acc[t][2], acc[t][3]);
    }
}

// ---------------------------------------------------------------------------
// Stage 2: warp per node, same 16-lane/uint4 two-half layout.
// out[v] = (sum_{e ni v} Zh[e]) * degV[v]   (fp32 output)
// ---------------------------------------------------------------------------
__global__ __launch_bounds__(256) void seg2_kernel(const float* __restrict__ degV,
                                                   float* __restrict__ out) {
    int gid  = blockIdx.x * blockDim.x + threadIdx.x;
    int v    = gid >> 5;
    int lane = gid & 31;
    if (v >= N_NODES) return;
    int half = lane >> 4;
    int sub  = lane & 15;

    int beg = g_rowptr_v[v];
    int end = g_rowptr_v[v + 1];
    const uint4* Zh4 = reinterpret_cast<const uint4*>(g_Zh);

    float acc[8];
#pragma unroll
    for (int j = 0; j < 8; j++) acc[j] = 0.f;

    int i = beg + half;
    for (; i + 2 < end; i += 4) {
        int d0 = __ldg(&g_dst_by_v[i + 0]);
        int d1 = __ldg(&g_dst_by_v[i + 2]);
        uint4 u0 = __ldg(&Zh4[(size_t)d0 * 16 + sub]);
        uint4 u1 = __ldg(&Zh4[(size_t)d1 * 16 + sub]);
#pragma unroll
        for (int j = 0; j < 2; j++) {
            uint4 u = (j == 0) ? u0 : u1;
            const __half2* h = reinterpret_cast<const __half2*>(&u);
#pragma unroll
            for (int q = 0; q < 4; q++) {
                float2 f = __half22float2(h[q]);
                acc[q * 2]     += f.x;
                acc[q * 2 + 1] += f.y;
            }
        }
    }
    for (; i < end; i += 2) {
        int d = __ldg(&g_dst_by_v[i]);
        uint4 u = __ldg(&Zh4[(size_t)d * 16 + sub]);
        const __half2* h = reinterpret_cast<const __half2*>(&u);
#pragma unroll
        for (int q = 0; q < 4; q++) {
            float2 f = __half22float2(h[q]);
            acc[q * 2]     += f.x;
            acc[q * 2 + 1] += f.y;
        }
    }

#pragma unroll
    for (int j = 0; j < 8; j++)
        acc[j] += __shfl_xor_sync(0xffffffffu, acc[j], 16);

    if (half == 0) {
        float sc = degV[v];
        float* o = out + (size_t)v * CH + sub * 8;
        *reinterpret_cast<float4*>(o) =
            make_float4(acc[0] * sc, acc[1] * sc, acc[2] * sc, acc[3] * sc);
        *reinterpret_cast<float4*>(o + 4) =
            make_float4(acc[4] * sc, acc[5] * sc, acc[6] * sc, acc[7] * sc);
    }
}

// ---------------------------------------------------------------------------
// Launch
// ---------------------------------------------------------------------------
extern "C" void kernel_launch(void* const* d_in, const int* in_sizes, int n_in,
                              void* d_out, int out_size) {
    const float* X    = (const float*)d_in[0];
    const float* Wlin = (const float*)d_in[1];
    const float* degE = (const float*)d_in[2];
    const float* degV = (const float*)d_in[3];
    const float* Wbuf = (const float*)d_in[4];
    const int*   src  = (const int*)d_in[5];
    const int*   dst  = (const int*)d_in[6];
    float*       out  = (float*)d_out;

    int *p_cnt_e, *p_cnt_v, *p_sync;
    cudaGetSymbolAddress((void**)&p_cnt_e, g_cnt_e);
    cudaGetSymbolAddress((void**)&p_cnt_v, g_cnt_v);
    cudaGetSymbolAddress((void**)&p_sync,  g_sync);

    static_assert(2 * 128 * GS * sizeof(__half) == 69632, "smem size");
    cudaFuncSetAttribute(gemm_hmma_kernel,
                         cudaFuncAttributeMaxDynamicSharedMemorySize, 69632);

    // 1. zero counters + sync flags
    cudaMemsetAsync(p_cnt_e, 0, N_HEDGES * sizeof(int));
    cudaMemsetAsync(p_cnt_v, 0, N_NODES  * sizeof(int));
    cudaMemsetAsync(p_sync,  0, 2 * sizeof(int));

    // 2. fp16 converts
    convertX_kernel<<<((size_t)N_NODES * CH / 8 + 255) / 256, 256>>>(X);
    convertW_kernel<<<(CH * CH / 8 + 255) / 256, 256>>>(Wlin);

    // 3. CSR build: histogram -> one-pass scan -> placement
    hist_kernel<<<(NNZ + 255) / 256, 256>>>(src, dst);
    scan_onepass_kernel<<<NBLK, 1024>>>();
    place_kernel<<<(NNZ + 255) / 256, 256>>>(src, dst);

    // 4. stage 1 (fp16 gather -> fp16 Yh)
    seg1_kernel<<<(N_HEDGES * 32 + 255) / 256, 256>>>(degE, Wbuf);

    // 5. tensor-core GEMM Zh = Yh @ Wh
    gemm_hmma_kernel<<<(N_HEDGES + 127) / 128, 256, 69632>>>();

    // 6. stage 2 (fp16 gather -> fp32 out)
    seg2_kernel<<<(N_NODES * 32 + 255) / 256, 256>>>(degV, out);
}